// round 14
// baseline (speedup 1.0000x reference)
#include <cuda_runtime.h>
#include <cuda_bf16.h>

#define GRID_N 4
#define WIN    3
#define NWIN   (GRID_N - WIN + 1)   // 2
#define NCELL  (GRID_N * GRID_N)    // 16
#define B_MAX  4096

// ---------------- Fast path: H = W = 512 (R9 structure, proven best) -------
// One block per batch, 1024 threads. Threads [64c, 64c+64) own cell c
// (gy=c/4, gx=c%4); each warp lies fully inside one cell (2 warps/cell).
// Per-thread address is constant-stride: for thread j within the cell,
//   addr(k) = base + (j>>5)*128 + (j&31) + 256*k,   k = 0..63
// so the unrolled loop compiles to LDG [Rbase + imm] with zero per-iter
// index math. __ldcs: evict-first streaming for the zero-reuse 128MB.
__global__ __launch_bounds__(1024) void fused_512_kernel(
        const float4* __restrict__ in, float* __restrict__ out) {
    int b = blockIdx.x;
    int t = threadIdx.x;
    int cell = t >> 6;
    int j    = t & 63;
    int gy = cell >> 2;
    int gx = cell & 3;

    // float4 strides: batch 65536, gy 16384, gx 32; row 128.
    const float4* p = in + (size_t)b * 65536 + gy * 16384 + gx * 32
                         + (j >> 5) * 128 + (j & 31);

    float a0 = 0.0f, a1 = 0.0f;
#pragma unroll 16
    for (int k = 0; k < 64; k += 2) {              // 2 accumulators
        float4 v0 = __ldcs(p + (size_t)k * 256);
        float4 v1 = __ldcs(p + (size_t)(k + 1) * 256);
        a0 += (v0.x + v0.y) + (v0.z + v0.w);
        a1 += (v1.x + v1.y) + (v1.z + v1.w);
    }
    float acc = a0 + a1;

#pragma unroll
    for (int o = 16; o > 0; o >>= 1)
        acc += __shfl_down_sync(0xffffffffu, acc, o);

    __shared__ float wsum[32];
    if ((t & 31) == 0) wsum[t >> 5] = acc;
    __syncthreads();

    __shared__ float csum[NCELL];
    if (t < NCELL) csum[t] = wsum[2 * t] + wsum[2 * t + 1];
    __syncthreads();

    if (t == 0) {
        float win[NWIN * NWIN];
#pragma unroll
        for (int r = 0; r < NWIN; r++)
#pragma unroll
            for (int q = 0; q < NWIN; q++) {
                float s = 0.0f;
#pragma unroll
                for (int dr = 0; dr < WIN; dr++)
#pragma unroll
                    for (int dc = 0; dc < WIN; dc++)
                        s += csum[(r + dr) * GRID_N + (q + dc)];
                win[r * NWIN + q] = s;
            }
        float best = win[0];
        int bi = 0;
#pragma unroll
        for (int k = 1; k < NWIN * NWIN; k++)
            if (win[k] > best) { best = win[k]; bi = k; }

        out[b * 2 + 0] = (float)(bi >> 1);   // row (float32 output)
        out[b * 2 + 1] = (float)(bi & 1);    // col
    }
}

// ---------------- Generic fallback (any square H=W, H%4==0) ----------------
__device__ float g_cell[B_MAX * NCELL];

__global__ __launch_bounds__(256) void cell_sum_kernel(
        const float* __restrict__ in, int HW, int W, int gh, int gw) {
    int blk  = blockIdx.x;
    int cell = blk & (NCELL - 1);
    int b    = blk >> 4;
    int gx = cell & (GRID_N - 1);
    int gy = cell >> 2;

    const float* base = in + (size_t)b * HW + (size_t)(gy * gh) * W + (size_t)gx * gw;

    int t = threadIdx.x;
    int n = gh * gw;
    float acc = 0.0f;
    for (int i = t; i < n; i += 256) {
        int r = i / gw;
        int c = i - r * gw;
        acc += base[(size_t)r * W + c];
    }
    __shared__ float sh[256];
    sh[t] = acc;
    __syncthreads();
#pragma unroll
    for (int s = 128; s > 0; s >>= 1) {
        if (t < s) sh[t] += sh[t + s];
        __syncthreads();
    }
    if (t == 0) g_cell[blk] = sh[0];
}

__global__ void select_kernel(float* __restrict__ out, int B) {
    int b = blockIdx.x * blockDim.x + threadIdx.x;
    if (b >= B) return;
    float c[NCELL];
#pragma unroll
    for (int i = 0; i < NCELL; i++) c[i] = g_cell[b * NCELL + i];

    float win[NWIN * NWIN];
#pragma unroll
    for (int r = 0; r < NWIN; r++)
#pragma unroll
        for (int q = 0; q < NWIN; q++) {
            float s = 0.0f;
#pragma unroll
            for (int dr = 0; dr < WIN; dr++)
#pragma unroll
                for (int dc = 0; dc < WIN; dc++)
                    s += c[(r + dr) * GRID_N + (q + dc)];
            win[r * NWIN + q] = s;
        }
    float best = win[0];
    int bi = 0;
#pragma unroll
    for (int k = 1; k < NWIN * NWIN; k++)
        if (win[k] > best) { best = win[k]; bi = k; }

    out[b * 2 + 0] = (float)(bi / NWIN);
    out[b * 2 + 1] = (float)(bi % NWIN);
}

extern "C" void kernel_launch(void* const* d_in, const int* in_sizes, int n_in,
                              void* d_out, int out_size) {
    int best_i = 0;
    for (int i = 1; i < n_in; i++)
        if (in_sizes[i] > in_sizes[best_i]) best_i = i;
    const float* in = (const float*)d_in[best_i];
    float* out = (float*)d_out;

    int B = out_size / 2;
    if (B < 1) B = 1;
    long long HW = (long long)in_sizes[best_i] / B;

    if (HW == 512LL * 512LL) {
        fused_512_kernel<<<B, 1024>>>((const float4*)in, out);
    } else {
        if (B > B_MAX) B = B_MAX;
        int H = 1;
        while ((long long)(H + 1) * (H + 1) <= HW) H++;
        int W = H;
        cell_sum_kernel<<<B * NCELL, 256>>>(in, (int)HW, W, H / GRID_N, W / GRID_N);
        select_kernel<<<(B + 127) / 128, 128>>>(out, B);
    }
}

// round 15
// speedup vs baseline: 1.0422x; 1.0422x over previous
#include <cuda_runtime.h>
#include <cuda_bf16.h>

#define GRID_N 4
#define WIN    3
#define NWIN   (GRID_N - WIN + 1)   // 2
#define NCELL  (GRID_N * GRID_N)    // 16
#define B_MAX  4096

// ---------------- Fast path: H = W = 512 (R9 configuration — proven best) --
// One block per batch, 1024 threads. Threads [64c, 64c+64) own cell c
// (gy=c/4, gx=c%4); each warp lies fully inside one cell (2 warps/cell).
// Compile-time 64-iteration loop with explicit per-iteration index math:
// keeps many live load destinations -> ptxas front-batches LDGs (high
// MLP_p1, regs=64), which is what sustains DRAM ~74%. Do not "simplify".
// __ldcs: evict-first streaming loads for the zero-reuse 128MB stream.
__global__ __launch_bounds__(1024) void fused_512_kernel(
        const float4* __restrict__ in, float* __restrict__ out) {
    int b = blockIdx.x;
    int t = threadIdx.x;
    int cell = t >> 6;
    int j    = t & 63;
    int gy = cell >> 2;
    int gx = cell & 3;

    const float4* base = in + (size_t)b * 65536 + gy * 16384 + gx * 32;

    float acc = 0.0f;
#pragma unroll 16
    for (int k = 0; k < 64; k++) {
        int i   = k * 64 + j;
        int row = i >> 5;
        int c4  = i & 31;
        float4 v = __ldcs(&base[row * 128 + c4]);   // streaming load
        acc += (v.x + v.y) + (v.z + v.w);
    }
#pragma unroll
    for (int o = 16; o > 0; o >>= 1)
        acc += __shfl_down_sync(0xffffffffu, acc, o);

    __shared__ float wsum[32];
    if ((t & 31) == 0) wsum[t >> 5] = acc;
    __syncthreads();

    __shared__ float csum[NCELL];
    if (t < NCELL) csum[t] = wsum[2 * t] + wsum[2 * t + 1];
    __syncthreads();

    if (t == 0) {
        float win[NWIN * NWIN];
#pragma unroll
        for (int r = 0; r < NWIN; r++)
#pragma unroll
            for (int q = 0; q < NWIN; q++) {
                float s = 0.0f;
#pragma unroll
                for (int dr = 0; dr < WIN; dr++)
#pragma unroll
                    for (int dc = 0; dc < WIN; dc++)
                        s += csum[(r + dr) * GRID_N + (q + dc)];
                win[r * NWIN + q] = s;
            }
        float best = win[0];
        int bi = 0;
#pragma unroll
        for (int k = 1; k < NWIN * NWIN; k++)
            if (win[k] > best) { best = win[k]; bi = k; }

        out[b * 2 + 0] = (float)(bi >> 1);   // row (float32 output)
        out[b * 2 + 1] = (float)(bi & 1);    // col
    }
}

// ---------------- Generic fallback (any square H=W, H%4==0) ----------------
__device__ float g_cell[B_MAX * NCELL];

__global__ __launch_bounds__(256) void cell_sum_kernel(
        const float* __restrict__ in, int HW, int W, int gh, int gw) {
    int blk  = blockIdx.x;
    int cell = blk & (NCELL - 1);
    int b    = blk >> 4;
    int gx = cell & (GRID_N - 1);
    int gy = cell >> 2;

    const float* base = in + (size_t)b * HW + (size_t)(gy * gh) * W + (size_t)gx * gw;

    int t = threadIdx.x;
    int n = gh * gw;
    float acc = 0.0f;
    for (int i = t; i < n; i += 256) {
        int r = i / gw;
        int c = i - r * gw;
        acc += base[(size_t)r * W + c];
    }
    __shared__ float sh[256];
    sh[t] = acc;
    __syncthreads();
#pragma unroll
    for (int s = 128; s > 0; s >>= 1) {
        if (t < s) sh[t] += sh[t + s];
        __syncthreads();
    }
    if (t == 0) g_cell[blk] = sh[0];
}

__global__ void select_kernel(float* __restrict__ out, int B) {
    int b = blockIdx.x * blockDim.x + threadIdx.x;
    if (b >= B) return;
    float c[NCELL];
#pragma unroll
    for (int i = 0; i < NCELL; i++) c[i] = g_cell[b * NCELL + i];

    float win[NWIN * NWIN];
#pragma unroll
    for (int r = 0; r < NWIN; r++)
#pragma unroll
        for (int q = 0; q < NWIN; q++) {
            float s = 0.0f;
#pragma unroll
            for (int dr = 0; dr < WIN; dr++)
#pragma unroll
                for (int dc = 0; dc < WIN; dc++)
                    s += c[(r + dr) * GRID_N + (q + dc)];
            win[r * NWIN + q] = s;
        }
    float best = win[0];
    int bi = 0;
#pragma unroll
    for (int k = 1; k < NWIN * NWIN; k++)
        if (win[k] > best) { best = win[k]; bi = k; }

    out[b * 2 + 0] = (float)(bi / NWIN);
    out[b * 2 + 1] = (float)(bi % NWIN);
}

extern "C" void kernel_launch(void* const* d_in, const int* in_sizes, int n_in,
                              void* d_out, int out_size) {
    int best_i = 0;
    for (int i = 1; i < n_in; i++)
        if (in_sizes[i] > in_sizes[best_i]) best_i = i;
    const float* in = (const float*)d_in[best_i];
    float* out = (float*)d_out;

    int B = out_size / 2;
    if (B < 1) B = 1;
    long long HW = (long long)in_sizes[best_i] / B;

    if (HW == 512LL * 512LL) {
        fused_512_kernel<<<B, 1024>>>((const float4*)in, out);
    } else {
        if (B > B_MAX) B = B_MAX;
        int H = 1;
        while ((long long)(H + 1) * (H + 1) <= HW) H++;
        int W = H;
        cell_sum_kernel<<<B * NCELL, 256>>>(in, (int)HW, W, H / GRID_N, W / GRID_N);
        select_kernel<<<(B + 127) / 128, 128>>>(out, B);
    }
}